// round 2
// baseline (speedup 1.0000x reference)
#include <cuda_runtime.h>

// Problem constants
#define BATCH 64
#define D 256
#define NTOK 4095

// Internal node values: nodes 0..2046, layout [node][batch][d]
__device__ float g_node_val[2047 * BATCH * D];
// Transposed weights, layout [k][j]: k 0..767 = W_in, 768..1023 = W1, 1024..1279 = W2
__device__ float g_Wt[1280 * D];

__global__ void transpose_weights(const float* __restrict__ W_in,
                                  const float* __restrict__ W1,
                                  const float* __restrict__ W2) {
    int idx = blockIdx.x * blockDim.x + threadIdx.x;
    if (idx >= 1280 * D) return;
    int k = idx / D, j = idx % D;
    float v;
    if (k < 768)        v = W_in[j * 768 + k];
    else if (k < 1024)  v = W1[j * 256 + (k - 768)];
    else                v = W2[j * 256 + (k - 1024)];
    g_Wt[idx] = v;
}

// Block = one tree node, M = 64 batch rows, N = 256 (full), fused 3-layer MLP.
// SMEM: hbuf[64][256] activation staging, Ws[32][256] weight k-chunk, As[64][40] input chunk, toks[3][64]
__global__ void __launch_bounds__(256, 2)
level_kernel(const int* __restrict__ tokens, const float* __restrict__ E,
             const float* __restrict__ b_in, const float* __restrict__ b1,
             const float* __restrict__ b2, float* __restrict__ d_out, int level)
{
    extern __shared__ float sm[];
    float* hbuf = sm;                    // 16384 floats
    float* Ws   = sm + 16384;            // 8192 floats
    float* As   = sm + 16384 + 8192;     // 64*40 = 2560 floats (padded stride 40)
    int*   toks = (int*)(sm + 16384 + 8192 + 2560); // 3*64 ints

    const int t  = threadIdx.x;
    const int tn = t & 31;
    const int tm = t >> 5;
    const int node = level - 1 + blockIdx.x;
    const bool leaf = (level == 1024);

    // Load token indices: roots always; children only at leaf level.
    if (t < BATCH) {
        toks[t] = tokens[t * NTOK + node];
    } else if (leaf && t < 2 * BATCH) {
        int b = t - BATCH;
        toks[t] = tokens[b * NTOK + (2 * node + 1)];
    } else if (leaf && t < 3 * BATCH) {
        int b = t - 2 * BATCH;
        toks[t] = tokens[b * NTOK + (2 * node + 2)];
    }
    // (first __syncthreads inside chunk loop covers this)

    float acc[8][8];

    // ================= Layer 1: K = 768 =================
    #pragma unroll
    for (int i = 0; i < 8; ++i)
        #pragma unroll
        for (int j = 0; j < 8; ++j) acc[i][j] = 0.f;

    for (int c = 0; c < 24; ++c) {
        __syncthreads();
        // Load W chunk (8192 floats, contiguous)
        {
            const float4* src = (const float4*)(g_Wt + c * 32 * D);
            float4* dst = (float4*)Ws;
            #pragma unroll
            for (int r = 0; r < 8; ++r) dst[t + r * 256] = src[t + r * 256];
        }
        // Load A chunk: 64 rows x 32 k
        {
            int b = t >> 2;
            int q = t & 3;
            const float* src;
            if (c < 8) {
                src = E + (size_t)toks[b] * D + c * 32;
            } else if (c < 16) {
                if (leaf) src = E + (size_t)toks[BATCH + b] * D + (c - 8) * 32;
                else      src = g_node_val + ((size_t)(2 * node + 1) * BATCH + b) * D + (c - 8) * 32;
            } else {
                if (leaf) src = E + (size_t)toks[2 * BATCH + b] * D + (c - 16) * 32;
                else      src = g_node_val + ((size_t)(2 * node + 2) * BATCH + b) * D + (c - 16) * 32;
            }
            float4 v0 = *(const float4*)(src + q * 4);
            float4 v1 = *(const float4*)(src + (q + 4) * 4);
            *(float4*)(As + b * 40 + q * 4)       = v0;
            *(float4*)(As + b * 40 + (q + 4) * 4) = v1;
        }
        __syncthreads();
        // Compute
        const float* Ap = As + tm * 8 * 40;
        #pragma unroll
        for (int kk = 0; kk < 32; ++kk) {
            float4 w0 = *(const float4*)(Ws + kk * 256 + tn * 4);
            float4 w1 = *(const float4*)(Ws + kk * 256 + tn * 4 + 128);
            #pragma unroll
            for (int i = 0; i < 8; ++i) {
                float a = Ap[i * 40 + kk];
                acc[i][0] += a * w0.x; acc[i][1] += a * w0.y;
                acc[i][2] += a * w0.z; acc[i][3] += a * w0.w;
                acc[i][4] += a * w1.x; acc[i][5] += a * w1.y;
                acc[i][6] += a * w1.z; acc[i][7] += a * w1.w;
            }
        }
    }

    // bias + ELU -> hbuf
    {
        float4 bb0 = *(const float4*)(b_in + tn * 4);
        float4 bb1 = *(const float4*)(b_in + tn * 4 + 128);
        float bv[8] = {bb0.x, bb0.y, bb0.z, bb0.w, bb1.x, bb1.y, bb1.z, bb1.w};
        #pragma unroll
        for (int i = 0; i < 8; ++i) {
            int row = tm * 8 + i;
            #pragma unroll
            for (int j = 0; j < 8; ++j) {
                int col = tn * 4 + (j & 3) + (j >> 2) * 128;
                float v = acc[i][j] + bv[j];
                v = v > 0.f ? v : (expf(v) - 1.f);
                hbuf[row * 256 + col] = v;
            }
        }
    }

    // ================= Layer 2: K = 256 =================
    #pragma unroll
    for (int i = 0; i < 8; ++i)
        #pragma unroll
        for (int j = 0; j < 8; ++j) acc[i][j] = 0.f;

    for (int c = 0; c < 8; ++c) {
        __syncthreads();  // (c==0: guards hbuf writes + prior Ws reads)
        {
            const float4* src = (const float4*)(g_Wt + (768 + c * 32) * D);
            float4* dst = (float4*)Ws;
            #pragma unroll
            for (int r = 0; r < 8; ++r) dst[t + r * 256] = src[t + r * 256];
        }
        __syncthreads();
        const float* Ap = hbuf + tm * 8 * 256 + c * 32;
        #pragma unroll
        for (int kk = 0; kk < 32; ++kk) {
            float4 w0 = *(const float4*)(Ws + kk * 256 + tn * 4);
            float4 w1 = *(const float4*)(Ws + kk * 256 + tn * 4 + 128);
            #pragma unroll
            for (int i = 0; i < 8; ++i) {
                float a = Ap[i * 256 + kk];
                acc[i][0] += a * w0.x; acc[i][1] += a * w0.y;
                acc[i][2] += a * w0.z; acc[i][3] += a * w0.w;
                acc[i][4] += a * w1.x; acc[i][5] += a * w1.y;
                acc[i][6] += a * w1.z; acc[i][7] += a * w1.w;
            }
        }
    }

    __syncthreads();  // all hbuf reads done before overwrite
    {
        float4 bb0 = *(const float4*)(b1 + tn * 4);
        float4 bb1 = *(const float4*)(b1 + tn * 4 + 128);
        float bv[8] = {bb0.x, bb0.y, bb0.z, bb0.w, bb1.x, bb1.y, bb1.z, bb1.w};
        #pragma unroll
        for (int i = 0; i < 8; ++i) {
            int row = tm * 8 + i;
            #pragma unroll
            for (int j = 0; j < 8; ++j) {
                int col = tn * 4 + (j & 3) + (j >> 2) * 128;
                float v = acc[i][j] + bv[j];
                v = v > 0.f ? v : (expf(v) - 1.f);
                hbuf[row * 256 + col] = v;
            }
        }
    }

    // ================= Layer 3: K = 256 =================
    #pragma unroll
    for (int i = 0; i < 8; ++i)
        #pragma unroll
        for (int j = 0; j < 8; ++j) acc[i][j] = 0.f;

    for (int c = 0; c < 8; ++c) {
        __syncthreads();
        {
            const float4* src = (const float4*)(g_Wt + (1024 + c * 32) * D);
            float4* dst = (float4*)Ws;
            #pragma unroll
            for (int r = 0; r < 8; ++r) dst[t + r * 256] = src[t + r * 256];
        }
        __syncthreads();
        const float* Ap = hbuf + tm * 8 * 256 + c * 32;
        #pragma unroll
        for (int kk = 0; kk < 32; ++kk) {
            float4 w0 = *(const float4*)(Ws + kk * 256 + tn * 4);
            float4 w1 = *(const float4*)(Ws + kk * 256 + tn * 4 + 128);
            #pragma unroll
            for (int i = 0; i < 8; ++i) {
                float a = Ap[i * 256 + kk];
                acc[i][0] += a * w0.x; acc[i][1] += a * w0.y;
                acc[i][2] += a * w0.z; acc[i][3] += a * w0.w;
                acc[i][4] += a * w1.x; acc[i][5] += a * w1.y;
                acc[i][6] += a * w1.z; acc[i][7] += a * w1.w;
            }
        }
    }

    // Epilogue: + b2 + residual root embedding, write out
    {
        float4 bb0 = *(const float4*)(b2 + tn * 4);
        float4 bb1 = *(const float4*)(b2 + tn * 4 + 128);
        float bv[8] = {bb0.x, bb0.y, bb0.z, bb0.w, bb1.x, bb1.y, bb1.z, bb1.w};
        #pragma unroll
        for (int i = 0; i < 8; ++i) {
            int row = tm * 8 + i;
            const float* Er = E + (size_t)toks[row] * D;
            float4 r0 = *(const float4*)(Er + tn * 4);
            float4 r1 = *(const float4*)(Er + tn * 4 + 128);
            float rv[8] = {r0.x, r0.y, r0.z, r0.w, r1.x, r1.y, r1.z, r1.w};
            #pragma unroll
            for (int j = 0; j < 8; ++j) {
                int col = tn * 4 + (j & 3) + (j >> 2) * 128;
                float v = acc[i][j] + bv[j] + rv[j];
                if (level == 1) {
                    d_out[row * D + col] = v;
                } else {
                    g_node_val[((size_t)node * BATCH + row) * D + col] = v;
                }
            }
        }
    }
}

extern "C" void kernel_launch(void* const* d_in, const int* in_sizes, int n_in,
                              void* d_out, int out_size) {
    const int*   tokens = (const int*)d_in[0];
    const float* E      = (const float*)d_in[1];
    const float* W_in   = (const float*)d_in[2];
    const float* b_in   = (const float*)d_in[3];
    const float* W1     = (const float*)d_in[4];
    const float* b1     = (const float*)d_in[5];
    const float* W2     = (const float*)d_in[6];
    const float* b2     = (const float*)d_in[7];
    float* out = (float*)d_out;

    transpose_weights<<<(1280 * D + 255) / 256, 256>>>(W_in, W1, W2);

    const int SMEM = (16384 + 8192 + 2560) * 4 + 3 * 64 * 4;  // 109312 B
    cudaFuncSetAttribute(level_kernel, cudaFuncAttributeMaxDynamicSharedMemorySize, SMEM);

    for (int level = 1024; level >= 1; level >>= 1) {
        level_kernel<<<level, 256, SMEM>>>(tokens, E, b_in, b1, b2, out, level);
    }
}

// round 3
// speedup vs baseline: 1.0502x; 1.0502x over previous
#include <cuda_runtime.h>

// Problem constants
#define BATCH 64
#define D 256
#define NTOK 4095

// Internal node values: nodes 0..2046, layout [node][batch][d]
__device__ float g_node_val[2047 * BATCH * D];
// Transposed weights, layout [k][j]: k 0..767 = W_in, 768..1023 = W1, 1024..1279 = W2
__device__ float g_Wt[1280 * D];

__global__ void transpose_weights(const float* __restrict__ W_in,
                                  const float* __restrict__ W1,
                                  const float* __restrict__ W2) {
    int idx = blockIdx.x * blockDim.x + threadIdx.x;
    if (idx >= 1280 * D) return;
    int k = idx / D, j = idx % D;
    float v;
    if (k < 768)        v = W_in[j * 768 + k];
    else if (k < 1024)  v = W1[j * 256 + (k - 768)];
    else                v = W2[j * 256 + (k - 1024)];
    g_Wt[idx] = v;
}

// Block = one tree node, M = 64 batch rows, N = 256 (full), fused 3-layer MLP.
// SMEM: hbuf[64][256] activation staging, Ws[32][256] weight k-chunk, As[64][40] input chunk, toks[3][64]
__global__ void __launch_bounds__(256, 2)
level_kernel(const int* __restrict__ tokens, const float* __restrict__ E,
             const float* __restrict__ b_in, const float* __restrict__ b1,
             const float* __restrict__ b2, float* __restrict__ d_out, int level)
{
    extern __shared__ float sm[];
    float* hbuf = sm;                    // 16384 floats
    float* Ws   = sm + 16384;            // 8192 floats
    float* As   = sm + 16384 + 8192;     // 64*40 = 2560 floats (padded stride 40)
    int*   toks = (int*)(sm + 16384 + 8192 + 2560); // 3*64 ints

    const int t  = threadIdx.x;
    const int tn = t & 31;
    const int tm = t >> 5;
    const int node = level - 1 + blockIdx.x;
    const bool leaf = (level == 1024);

    // Load token indices: roots always; children only at leaf level.
    if (t < BATCH) {
        toks[t] = tokens[t * NTOK + node];
    } else if (leaf && t < 2 * BATCH) {
        int b = t - BATCH;
        toks[t] = tokens[b * NTOK + (2 * node + 1)];
    } else if (leaf && t < 3 * BATCH) {
        int b = t - 2 * BATCH;
        toks[t] = tokens[b * NTOK + (2 * node + 2)];
    }
    // (first __syncthreads inside chunk loop covers this)

    float acc[8][8];

    // ================= Layer 1: K = 768 =================
    #pragma unroll
    for (int i = 0; i < 8; ++i)
        #pragma unroll
        for (int j = 0; j < 8; ++j) acc[i][j] = 0.f;

    for (int c = 0; c < 24; ++c) {
        __syncthreads();
        // Load W chunk (8192 floats, contiguous)
        {
            const float4* src = (const float4*)(g_Wt + c * 32 * D);
            float4* dst = (float4*)Ws;
            #pragma unroll
            for (int r = 0; r < 8; ++r) dst[t + r * 256] = src[t + r * 256];
        }
        // Load A chunk: 64 rows x 32 k
        {
            int b = t >> 2;
            int q = t & 3;
            const float* src;
            if (c < 8) {
                src = E + (size_t)toks[b] * D + c * 32;
            } else if (c < 16) {
                if (leaf) src = E + (size_t)toks[BATCH + b] * D + (c - 8) * 32;
                else      src = g_node_val + ((size_t)(2 * node + 1) * BATCH + b) * D + (c - 8) * 32;
            } else {
                if (leaf) src = E + (size_t)toks[2 * BATCH + b] * D + (c - 16) * 32;
                else      src = g_node_val + ((size_t)(2 * node + 2) * BATCH + b) * D + (c - 16) * 32;
            }
            float4 v0 = *(const float4*)(src + q * 4);
            float4 v1 = *(const float4*)(src + (q + 4) * 4);
            *(float4*)(As + b * 40 + q * 4)       = v0;
            *(float4*)(As + b * 40 + (q + 4) * 4) = v1;
        }
        __syncthreads();
        // Compute
        const float* Ap = As + tm * 8 * 40;
        #pragma unroll
        for (int kk = 0; kk < 32; ++kk) {
            float4 w0 = *(const float4*)(Ws + kk * 256 + tn * 4);
            float4 w1 = *(const float4*)(Ws + kk * 256 + tn * 4 + 128);
            #pragma unroll
            for (int i = 0; i < 8; ++i) {
                float a = Ap[i * 40 + kk];
                acc[i][0] += a * w0.x; acc[i][1] += a * w0.y;
                acc[i][2] += a * w0.z; acc[i][3] += a * w0.w;
                acc[i][4] += a * w1.x; acc[i][5] += a * w1.y;
                acc[i][6] += a * w1.z; acc[i][7] += a * w1.w;
            }
        }
    }

    // bias + ELU -> hbuf
    {
        float4 bb0 = *(const float4*)(b_in + tn * 4);
        float4 bb1 = *(const float4*)(b_in + tn * 4 + 128);
        float bv[8] = {bb0.x, bb0.y, bb0.z, bb0.w, bb1.x, bb1.y, bb1.z, bb1.w};
        #pragma unroll
        for (int i = 0; i < 8; ++i) {
            int row = tm * 8 + i;
            #pragma unroll
            for (int j = 0; j < 8; ++j) {
                int col = tn * 4 + (j & 3) + (j >> 2) * 128;
                float v = acc[i][j] + bv[j];
                v = v > 0.f ? v : (expf(v) - 1.f);
                hbuf[row * 256 + col] = v;
            }
        }
    }

    // ================= Layer 2: K = 256 =================
    #pragma unroll
    for (int i = 0; i < 8; ++i)
        #pragma unroll
        for (int j = 0; j < 8; ++j) acc[i][j] = 0.f;

    for (int c = 0; c < 8; ++c) {
        __syncthreads();  // (c==0: guards hbuf writes + prior Ws reads)
        {
            const float4* src = (const float4*)(g_Wt + (768 + c * 32) * D);
            float4* dst = (float4*)Ws;
            #pragma unroll
            for (int r = 0; r < 8; ++r) dst[t + r * 256] = src[t + r * 256];
        }
        __syncthreads();
        const float* Ap = hbuf + tm * 8 * 256 + c * 32;
        #pragma unroll
        for (int kk = 0; kk < 32; ++kk) {
            float4 w0 = *(const float4*)(Ws + kk * 256 + tn * 4);
            float4 w1 = *(const float4*)(Ws + kk * 256 + tn * 4 + 128);
            #pragma unroll
            for (int i = 0; i < 8; ++i) {
                float a = Ap[i * 256 + kk];
                acc[i][0] += a * w0.x; acc[i][1] += a * w0.y;
                acc[i][2] += a * w0.z; acc[i][3] += a * w0.w;
                acc[i][4] += a * w1.x; acc[i][5] += a * w1.y;
                acc[i][6] += a * w1.z; acc[i][7] += a * w1.w;
            }
        }
    }

    __syncthreads();  // all hbuf reads done before overwrite
    {
        float4 bb0 = *(const float4*)(b1 + tn * 4);
        float4 bb1 = *(const float4*)(b1 + tn * 4 + 128);
        float bv[8] = {bb0.x, bb0.y, bb0.z, bb0.w, bb1.x, bb1.y, bb1.z, bb1.w};
        #pragma unroll
        for (int i = 0; i < 8; ++i) {
            int row = tm * 8 + i;
            #pragma unroll
            for (int j = 0; j < 8; ++j) {
                int col = tn * 4 + (j & 3) + (j >> 2) * 128;
                float v = acc[i][j] + bv[j];
                v = v > 0.f ? v : (expf(v) - 1.f);
                hbuf[row * 256 + col] = v;
            }
        }
    }

    // ================= Layer 3: K = 256 =================
    #pragma unroll
    for (int i = 0; i < 8; ++i)
        #pragma unroll
        for (int j = 0; j < 8; ++j) acc[i][j] = 0.f;

    for (int c = 0; c < 8; ++c) {
        __syncthreads();
        {
            const float4* src = (const float4*)(g_Wt + (1024 + c * 32) * D);
            float4* dst = (float4*)Ws;
            #pragma unroll
            for (int r = 0; r < 8; ++r) dst[t + r * 256] = src[t + r * 256];
        }
        __syncthreads();
        const float* Ap = hbuf + tm * 8 * 256 + c * 32;
        #pragma unroll
        for (int kk = 0; kk < 32; ++kk) {
            float4 w0 = *(const float4*)(Ws + kk * 256 + tn * 4);
            float4 w1 = *(const float4*)(Ws + kk * 256 + tn * 4 + 128);
            #pragma unroll
            for (int i = 0; i < 8; ++i) {
                float a = Ap[i * 256 + kk];
                acc[i][0] += a * w0.x; acc[i][1] += a * w0.y;
                acc[i][2] += a * w0.z; acc[i][3] += a * w0.w;
                acc[i][4] += a * w1.x; acc[i][5] += a * w1.y;
                acc[i][6] += a * w1.z; acc[i][7] += a * w1.w;
            }
        }
    }

    // Epilogue: + b2 + residual root embedding, write out
    {
        float4 bb0 = *(const float4*)(b2 + tn * 4);
        float4 bb1 = *(const float4*)(b2 + tn * 4 + 128);
        float bv[8] = {bb0.x, bb0.y, bb0.z, bb0.w, bb1.x, bb1.y, bb1.z, bb1.w};
        #pragma unroll
        for (int i = 0; i < 8; ++i) {
            int row = tm * 8 + i;
            const float* Er = E + (size_t)toks[row] * D;
            float4 r0 = *(const float4*)(Er + tn * 4);
            float4 r1 = *(const float4*)(Er + tn * 4 + 128);
            float rv[8] = {r0.x, r0.y, r0.z, r0.w, r1.x, r1.y, r1.z, r1.w};
            #pragma unroll
            for (int j = 0; j < 8; ++j) {
                int col = tn * 4 + (j & 3) + (j >> 2) * 128;
                float v = acc[i][j] + bv[j] + rv[j];
                if (level == 1) {
                    d_out[row * D + col] = v;
                } else {
                    g_node_val[((size_t)node * BATCH + row) * D + col] = v;
                }
            }
        }
    }
}

extern "C" void kernel_launch(void* const* d_in, const int* in_sizes, int n_in,
                              void* d_out, int out_size) {
    const int*   tokens = (const int*)d_in[0];
    const float* E      = (const float*)d_in[1];
    const float* W_in   = (const float*)d_in[2];
    const float* b_in   = (const float*)d_in[3];
    const float* W1     = (const float*)d_in[4];
    const float* b1     = (const float*)d_in[5];
    const float* W2     = (const float*)d_in[6];
    const float* b2     = (const float*)d_in[7];
    float* out = (float*)d_out;

    transpose_weights<<<(1280 * D + 255) / 256, 256>>>(W_in, W1, W2);

    const int SMEM = (16384 + 8192 + 2560) * 4 + 3 * 64 * 4;  // 109312 B
    cudaFuncSetAttribute(level_kernel, cudaFuncAttributeMaxDynamicSharedMemorySize, SMEM);

    for (int level = 1024; level >= 1; level >>= 1) {
        level_kernel<<<level, 256, SMEM>>>(tokens, E, b_in, b1, b2, out, level);
    }
}

// round 5
// speedup vs baseline: 1.8844x; 1.7942x over previous
#include <cuda_runtime.h>
#include <cuda_bf16.h>
#include <cstdint>

#define BATCH 64
#define D 256
#define NTOK 4095
#define NCH 40            // 24 (layer1 K=768) + 8 + 8, K-chunk = 32
#define WCHUNK_BYTES 40960  // 2 parts x 256 rows x 80B (32 bf16 + pad)

__device__ float g_node_val[2047 * BATCH * D];
__device__ __align__(256) unsigned char g_W[NCH * WCHUNK_BYTES];

// ---------------- SMEM layout (bytes) ----------------
#define WOFF     0              // 2 slots x 40960 = 81920
#define BIGOFF   81920          // 135680: As ring (layer1) / Af (layers2-3) / stage (final)
#define BIASOFF  217600         // 768 floats
#define RPTROFF  220672         // 384 pointers
#define SMEM_TOTAL 223744
// Within BIG region:
//   As ring: slot*20480, parts hi/lo at +0/+10240, row stride 80B (layer 1 only)
//   Af:      hi at +0, lo at +67584, row stride 528B (264 bf16)  (layers 2-3)
//   stage:   float[128][265]                                      (final epilogue)

__device__ __forceinline__ uint32_t smem_u32(const void* p) {
    uint32_t a;
    asm("{ .reg .u64 t; cvta.to.shared.u64 t, %1; cvt.u32.u64 %0, t; }" : "=r"(a) : "l"(p));
    return a;
}
__device__ __forceinline__ void cp_async16(uint32_t dst, const void* src) {
    asm volatile("cp.async.cg.shared.global [%0], [%1], 16;" :: "r"(dst), "l"(src) : "memory");
}
__device__ __forceinline__ void cp_commit() { asm volatile("cp.async.commit_group;" ::: "memory"); }
template<int N> __device__ __forceinline__ void cp_wait() {
    asm volatile("cp.async.wait_group %0;" :: "n"(N) : "memory");
}
__device__ __forceinline__ void mma16816(float d[4], uint32_t a0, uint32_t a1, uint32_t a2, uint32_t a3,
                                         uint32_t b0, uint32_t b1) {
    asm volatile("mma.sync.aligned.m16n8k16.row.col.f32.bf16.bf16.f32 "
                 "{%0,%1,%2,%3}, {%4,%5,%6,%7}, {%8,%9}, {%0,%1,%2,%3};"
                 : "+f"(d[0]), "+f"(d[1]), "+f"(d[2]), "+f"(d[3])
                 : "r"(a0), "r"(a1), "r"(a2), "r"(a3), "r"(b0), "r"(b1));
}
__device__ __forceinline__ uint32_t b2u(__nv_bfloat162 v) { return *reinterpret_cast<uint32_t*>(&v); }
__device__ __forceinline__ void split2(float x, float y, uint32_t& h, uint32_t& l) {
    __nv_bfloat162 hh = __floats2bfloat162_rn(x, y);
    __nv_bfloat162 ll = __floats2bfloat162_rn(x - __bfloat162float(hh.x),
                                              y - __bfloat162float(hh.y));
    h = b2u(hh); l = b2u(ll);
}

// -------- weight prep: fp32 -> hi/lo bf16, fragment-ready padded tiles --------
// g_W word layout: ((chunk*2 + part)*256 + n)*20 + kp   (kp 0..15 used, 16..19 pad)
__global__ void prep_weights(const float* __restrict__ W_in,
                             const float* __restrict__ W1,
                             const float* __restrict__ W2) {
    int idx = blockIdx.x * blockDim.x + threadIdx.x;
    if (idx >= NCH * 2 * 256 * 16) return;
    int kp   = idx & 15;
    int n    = (idx >> 4) & 255;
    int part = (idx >> 12) & 1;
    int c    = idx >> 13;
    const float* Wsrc; int K, kbase;
    if (c < 24)      { Wsrc = W_in; K = 768; kbase = c * 32; }
    else if (c < 32) { Wsrc = W1;   K = 256; kbase = (c - 24) * 32; }
    else             { Wsrc = W2;   K = 256; kbase = (c - 32) * 32; }
    int k = kbase + kp * 2;
    float w0 = Wsrc[n * K + k];
    float w1 = Wsrc[n * K + k + 1];
    uint32_t h, l;
    split2(w0, w1, h, l);
    unsigned* dst = (unsigned*)g_W;
    dst[((c * 2 + part) * 256 + n) * 20 + kp] = (part == 0) ? h : l;
}

__global__ void __launch_bounds__(256, 1)
level_kernel(const int* __restrict__ tokens, const float* __restrict__ E,
             const float* __restrict__ b_in, const float* __restrict__ b1,
             const float* __restrict__ b2, float* __restrict__ d_out, int level)
{
    extern __shared__ char smem[];
    float* bias = (float*)(smem + BIASOFF);
    const float** rowptr = (const float**)(smem + RPTROFF);
    float* stage = (float*)(smem + BIGOFF);
    const uint32_t sbW = smem_u32(smem + WOFF);

    const int tid  = threadIdx.x;
    const int wid  = tid >> 5;
    const int lane = tid & 31;
    const int g    = lane >> 2;
    const int tig  = lane & 3;
    const int wm   = wid & 1;        // M half (64 rows)
    const int wn   = wid >> 1;       // N quarter (64 cols)
    const int nA   = level - 1 + 2 * blockIdx.x;
    const bool leaf = (level == 1024);

    // biases + per-row source pointers
    bias[tid]       = b_in[tid];
    bias[256 + tid] = b1[tid];
    bias[512 + tid] = b2[tid];
    if (tid < 128) {
        int row = tid;
        int node = nA + (row >> 6);
        int b = row & 63;
        rowptr[row] = E + (size_t)tokens[b * NTOK + node] * D;
        if (leaf) {
            rowptr[128 + row] = E + (size_t)tokens[b * NTOK + 2 * node + 1] * D;
            rowptr[256 + row] = E + (size_t)tokens[b * NTOK + 2 * node + 2] * D;
        } else {
            rowptr[128 + row] = g_node_val + ((size_t)(2 * node + 1) * BATCH + b) * D;
            rowptr[256 + row] = g_node_val + ((size_t)(2 * node + 2) * BATCH + b) * D;
        }
    }

    float acc[4][8][4];
    #pragma unroll
    for (int i = 0; i < 4; ++i)
        #pragma unroll
        for (int j = 0; j < 8; ++j)
            #pragma unroll
            for (int q = 0; q < 4; ++q) acc[i][j][q] = 0.f;

    // prefetch W chunk 0
    {
        const char* src = (const char*)g_W;
        #pragma unroll
        for (int r = 0; r < 10; ++r)
            cp_async16(sbW + tid * 16 + r * 4096, src + tid * 16 + r * 4096);
        cp_commit();
    }
    __syncthreads();   // rowptr/bias visible

    for (int gc = 0; gc < NCH; ++gc) {
        const int slot = gc & 1;

        // prefetch next W chunk into the other slot
        if (gc + 1 < NCH) {
            const char* src = (const char*)g_W + (size_t)(gc + 1) * WCHUNK_BYTES;
            uint32_t dst = sbW + ((gc + 1) & 1) * WCHUNK_BYTES;
            #pragma unroll
            for (int r = 0; r < 10; ++r)
                cp_async16(dst + tid * 16 + r * 4096, src + tid * 16 + r * 4096);
            cp_commit();
        }

        // layer-1: gather + split-convert A chunk into As[slot]
        if (gc < 24) {
            int seg  = gc >> 3;
            int koff = (gc & 7) * 32;
            int row  = tid >> 1;
            int half = tid & 1;
            const float* src = rowptr[seg * 128 + row] + koff + half * 16;
            float4 f0 = ((const float4*)src)[0];
            float4 f1 = ((const float4*)src)[1];
            float4 f2 = ((const float4*)src)[2];
            float4 f3 = ((const float4*)src)[3];
            uint32_t h[8], l[8];
            split2(f0.x, f0.y, h[0], l[0]); split2(f0.z, f0.w, h[1], l[1]);
            split2(f1.x, f1.y, h[2], l[2]); split2(f1.z, f1.w, h[3], l[3]);
            split2(f2.x, f2.y, h[4], l[4]); split2(f2.z, f2.w, h[5], l[5]);
            split2(f3.x, f3.y, h[6], l[6]); split2(f3.z, f3.w, h[7], l[7]);
            char* dst = smem + BIGOFF + slot * 20480 + row * 80 + half * 32;
            ((uint4*)dst)[0] = make_uint4(h[0], h[1], h[2], h[3]);
            ((uint4*)(dst + 16))[0] = make_uint4(h[4], h[5], h[6], h[7]);
            ((uint4*)(dst + 10240))[0] = make_uint4(l[0], l[1], l[2], l[3]);
            ((uint4*)(dst + 10256))[0] = make_uint4(l[4], l[5], l[6], l[7]);
        }

        if (gc + 1 < NCH) cp_wait<1>(); else cp_wait<0>();
        __syncthreads();

        // ---------- compute chunk (K=32, two k16 steps) ----------
        const char* wSlot = smem + WOFF + slot * WCHUNK_BYTES;
        #pragma unroll
        for (int k0 = 0; k0 < 32; k0 += 16) {
            uint32_t Ah[4][4], Al[4][4];
            if (gc < 24) {
                const char* aBase = smem + BIGOFF + slot * 20480;
                int kb = (k0 + tig * 2) * 2;
                #pragma unroll
                for (int i = 0; i < 4; ++i) {
                    const char* ar = aBase + (wm * 64 + i * 16 + g) * 80 + kb;
                    Ah[i][0] = *(const uint32_t*)(ar);
                    Ah[i][1] = *(const uint32_t*)(ar + 640);
                    Ah[i][2] = *(const uint32_t*)(ar + 16);
                    Ah[i][3] = *(const uint32_t*)(ar + 656);
                    Al[i][0] = *(const uint32_t*)(ar + 10240);
                    Al[i][1] = *(const uint32_t*)(ar + 10880);
                    Al[i][2] = *(const uint32_t*)(ar + 10256);
                    Al[i][3] = *(const uint32_t*)(ar + 10896);
                }
            } else {
                const char* aBase = smem + BIGOFF;
                int kb = (((gc - 24) & 7) * 32 + k0 + tig * 2) * 2;
                #pragma unroll
                for (int i = 0; i < 4; ++i) {
                    const char* ar = aBase + (wm * 64 + i * 16 + g) * 528 + kb;
                    Ah[i][0] = *(const uint32_t*)(ar);
                    Ah[i][1] = *(const uint32_t*)(ar + 4224);
                    Ah[i][2] = *(const uint32_t*)(ar + 16);
                    Ah[i][3] = *(const uint32_t*)(ar + 4240);
                    Al[i][0] = *(const uint32_t*)(ar + 67584);
                    Al[i][1] = *(const uint32_t*)(ar + 71808);
                    Al[i][2] = *(const uint32_t*)(ar + 67600);
                    Al[i][3] = *(const uint32_t*)(ar + 71824);
                }
            }
            int kwb = (k0 + tig * 2) * 2;
            #pragma unroll
            for (int j = 0; j < 8; ++j) {
                const char* wr = wSlot + (wn * 64 + j * 8 + g) * 80 + kwb;
                uint32_t bh0 = *(const uint32_t*)(wr);
                uint32_t bh1 = *(const uint32_t*)(wr + 16);
                uint32_t bl0 = *(const uint32_t*)(wr + 20480);
                uint32_t bl1 = *(const uint32_t*)(wr + 20496);
                #pragma unroll
                for (int i = 0; i < 4; ++i) {
                    mma16816(acc[i][j], Ah[i][0], Ah[i][1], Ah[i][2], Ah[i][3], bh0, bh1);
                    mma16816(acc[i][j], Ah[i][0], Ah[i][1], Ah[i][2], Ah[i][3], bl0, bl1);
                    mma16816(acc[i][j], Al[i][0], Al[i][1], Al[i][2], Al[i][3], bh0, bh1);
                }
            }
        }
        __syncthreads();

        // ---------- mid epilogue after layers 1 and 2 ----------
        if (gc == 23 || gc == 31) {
            const float* bp = bias + ((gc == 23) ? 0 : 256);
            char* afHi = smem + BIGOFF;
            #pragma unroll
            for (int i = 0; i < 4; ++i) {
                #pragma unroll
                for (int j = 0; j < 8; ++j) {
                    int r0 = wm * 64 + i * 16 + g;
                    int cb = wn * 64 + j * 8 + tig * 2;
                    float bv0 = bp[cb], bv1 = bp[cb + 1];
                    float v0 = acc[i][j][0] + bv0, v1 = acc[i][j][1] + bv1;
                    float v2 = acc[i][j][2] + bv0, v3 = acc[i][j][3] + bv1;
                    v0 = v0 > 0.f ? v0 : (__expf(v0) - 1.f);
                    v1 = v1 > 0.f ? v1 : (__expf(v1) - 1.f);
                    v2 = v2 > 0.f ? v2 : (__expf(v2) - 1.f);
                    v3 = v3 > 0.f ? v3 : (__expf(v3) - 1.f);
                    uint32_t h, l;
                    split2(v0, v1, h, l);
                    *(uint32_t*)(afHi + r0 * 528 + cb * 2) = h;
                    *(uint32_t*)(afHi + 67584 + r0 * 528 + cb * 2) = l;
                    split2(v2, v3, h, l);
                    *(uint32_t*)(afHi + (r0 + 8) * 528 + cb * 2) = h;
                    *(uint32_t*)(afHi + 67584 + (r0 + 8) * 528 + cb * 2) = l;
                    acc[i][j][0] = acc[i][j][1] = acc[i][j][2] = acc[i][j][3] = 0.f;
                }
            }
            __syncthreads();
        }
    }

    // ---------- final epilogue ----------
    {
        #pragma unroll
        for (int i = 0; i < 4; ++i) {
            #pragma unroll
            for (int j = 0; j < 8; ++j) {
                int r0 = wm * 64 + i * 16 + g;
                int cb = wn * 64 + j * 8 + tig * 2;
                float bv0 = bias[512 + cb], bv1 = bias[512 + cb + 1];
                stage[r0 * 265 + cb]           = acc[i][j][0] + bv0;
                stage[r0 * 265 + cb + 1]       = acc[i][j][1] + bv1;
                stage[(r0 + 8) * 265 + cb]     = acc[i][j][2] + bv0;
                stage[(r0 + 8) * 265 + cb + 1] = acc[i][j][3] + bv1;
            }
        }
    }
    __syncthreads();
    // residual (coalesced E reads) + coalesced store
    #pragma unroll 1
    for (int it = 0; it < 32; ++it) {
        int lin = it * 256 + tid;        // float4 index over [128][64]
        int row = lin >> 6;
        int c4 = lin & 63;
        if (level == 1 && row >= 64) continue;
        float4 e = ((const float4*)rowptr[row])[c4];
        const float* sp = stage + row * 265 + c4 * 4;
        float4 ov = make_float4(sp[0] + e.x, sp[1] + e.y, sp[2] + e.z, sp[3] + e.w);
        if (level == 1) {
            ((float4*)(d_out + (size_t)row * D))[c4] = ov;
        } else {
            int node = nA + (row >> 6);
            ((float4*)(g_node_val + ((size_t)node * BATCH + (row & 63)) * D))[c4] = ov;
        }
    }
}

extern "C" void kernel_launch(void* const* d_in, const int* in_sizes, int n_in,
                              void* d_out, int out_size) {
    const int*   tokens = (const int*)d_in[0];
    const float* E      = (const float*)d_in[1];
    const float* W_in   = (const float*)d_in[2];
    const float* b_in   = (const float*)d_in[3];
    const float* W1     = (const float*)d_in[4];
    const float* b1     = (const float*)d_in[5];
    const float* W2     = (const float*)d_in[6];
    const float* b2     = (const float*)d_in[7];
    float* out = (float*)d_out;

    cudaFuncSetAttribute(level_kernel, cudaFuncAttributeMaxDynamicSharedMemorySize, SMEM_TOTAL);

    prep_weights<<<(NCH * 2 * 256 * 16) / 256, 256>>>(W_in, W1, W2);

    for (int level = 1024; level >= 1; level >>= 1) {
        int grid = (level > 1) ? (level / 2) : 1;
        level_kernel<<<grid, 256, SMEM_TOTAL>>>(tokens, E, b_in, b1, b2, out, level);
    }
}

// round 6
// speedup vs baseline: 2.8175x; 1.4952x over previous
#include <cuda_runtime.h>
#include <cuda_bf16.h>
#include <cstdint>

#define BATCH 64
#define D 256
#define NTOK 4095
#define NCH 40            // 24 (layer1 K=768) + 8 (layer2) + 8 (layer3), K-chunk = 32
#define WCHUNK 32768      // bytes per W chunk (frag-major, hi+lo packed)

__device__ float g_node_val[2047 * BATCH * D];
__device__ __align__(256) uint4 g_W[NCH * 2048];   // 1.25 MB

// ---------------- helpers ----------------
__device__ __forceinline__ uint32_t smem_u32(const void* p) {
    uint32_t a;
    asm("{ .reg .u64 t; cvta.to.shared.u64 t, %1; cvt.u32.u64 %0, t; }" : "=r"(a) : "l"(p));
    return a;
}
__device__ __forceinline__ void cp_async16(uint32_t dst, const void* src) {
    asm volatile("cp.async.cg.shared.global [%0], [%1], 16;" :: "r"(dst), "l"(src) : "memory");
}
__device__ __forceinline__ void cp_commit() { asm volatile("cp.async.commit_group;" ::: "memory"); }
template<int N> __device__ __forceinline__ void cp_wait() {
    asm volatile("cp.async.wait_group %0;" :: "n"(N) : "memory");
}
__device__ __forceinline__ void mma16816(float d[4], uint32_t a0, uint32_t a1, uint32_t a2, uint32_t a3,
                                         uint32_t b0, uint32_t b1) {
    asm volatile("mma.sync.aligned.m16n8k16.row.col.f32.bf16.bf16.f32 "
                 "{%0,%1,%2,%3}, {%4,%5,%6,%7}, {%8,%9}, {%0,%1,%2,%3};"
                 : "+f"(d[0]), "+f"(d[1]), "+f"(d[2]), "+f"(d[3])
                 : "r"(a0), "r"(a1), "r"(a2), "r"(a3), "r"(b0), "r"(b1));
}
__device__ __forceinline__ uint32_t b2u(__nv_bfloat162 v) { return *reinterpret_cast<uint32_t*>(&v); }
__device__ __forceinline__ void split2(float x, float y, uint32_t& h, uint32_t& l) {
    __nv_bfloat162 hh = __floats2bfloat162_rn(x, y);
    __nv_bfloat162 ll = __floats2bfloat162_rn(x - __bfloat162float(hh.x),
                                              y - __bfloat162float(hh.y));
    h = b2u(hh); l = b2u(ll);
}

// -------- weight prep: fp32 -> hi/lo bf16, frag-major (one LDS.128 = hi+lo B frags) --------
// g_W[((gc*2+s)*32 + jt)*32 + lane] = {b0h, b1h, b0l, b1l}
//   n = jt*8 + lane/4;  k = kbase(gc) + s*16 + (lane%4)*2 (+8 for b1)
__global__ void prep_weights(const float* __restrict__ W_in,
                             const float* __restrict__ W1,
                             const float* __restrict__ W2) {
    int idx = blockIdx.x * 256 + threadIdx.x;
    if (idx >= NCH * 2048) return;
    int lane = idx & 31;
    int jt   = (idx >> 5) & 31;
    int s    = (idx >> 10) & 1;
    int gcw  = idx >> 11;
    int n  = jt * 8 + (lane >> 2);
    int tg = lane & 3;
    const float* Wsrc; int K, kb;
    if (gcw < 24)      { Wsrc = W_in; K = 768; kb = gcw * 32; }
    else if (gcw < 32) { Wsrc = W1;   K = 256; kb = (gcw - 24) * 32; }
    else               { Wsrc = W2;   K = 256; kb = (gcw - 32) * 32; }
    int k0 = kb + s * 16 + tg * 2;
    uint32_t h0, l0, h1, l1;
    split2(Wsrc[n * K + k0],     Wsrc[n * K + k0 + 1], h0, l0);
    split2(Wsrc[n * K + k0 + 8], Wsrc[n * K + k0 + 9], h1, l1);
    g_W[idx] = make_uint4(h0, h1, l0, l1);
}

// ---------------- fused 3-layer MLP kernel, templated on block M ----------------
// SMEM: [0, 65536) W ring (2 x 32KB, frag-major)
//       [65536, 65536+BIGSZ) BIG: As ring (layer1) / Af resident (layers 2-3) / stage (final)
//       then bias (768 f), rowptr (3*MROWS ptrs)
// A frag-major layout (per part p, tile t, kstep/s, lane): 16B = {a0,a1,a2,a3}
template<int MROWS>
__global__ void __launch_bounds__(256, 1)
level_kernel(const int* __restrict__ tokens, const float* __restrict__ E,
             const float* __restrict__ b_in, const float* __restrict__ b1,
             const float* __restrict__ b2, float* __restrict__ d_out, int level)
{
    constexpr int NT    = MROWS / 16;              // A m-tiles
    constexpr int JN    = (MROWS == 128) ? 8 : 4;  // n8-tiles per warp
    constexpr int ASLOT = NT * 2048;               // bytes per layer-1 A slot (hi+lo)
    constexpr int BIGOFF = 65536;
    constexpr int BIGSZ  = MROWS * 265 * 4;        // stage dominates (>= Af = 2*NT*8192)
    constexpr int BIASOFF = BIGOFF + BIGSZ;
    constexpr int RPTROFF = BIASOFF + 3072;

    extern __shared__ char smem[];
    float* bias = (float*)(smem + BIASOFF);
    const float** rowptr = (const float**)(smem + RPTROFF);
    float* stage = (float*)(smem + BIGOFF);
    char* As = smem + BIGOFF;
    char* Af = smem + BIGOFF;
    const uint32_t sbW = smem_u32(smem);

    const int tid  = threadIdx.x;
    const int wid  = tid >> 5;
    const int lane = tid & 31;
    const int g    = lane >> 2;
    const int tig  = lane & 3;
    const int wm   = (MROWS == 128) ? (wid & 1) : 0;
    const int wn   = (MROWS == 128) ? (wid >> 1) : wid;
    const int nA   = level - 1 + (MROWS / 64) * blockIdx.x;

    bias[tid]       = b_in[tid];
    bias[256 + tid] = b1[tid];
    bias[512 + tid] = b2[tid];
    if (tid < MROWS) {
        int row = tid;
        int node = nA + (row >> 6);
        int b = row & 63;
        rowptr[row] = E + (size_t)tokens[b * NTOK + node] * D;
        if (level == 1024) {
            rowptr[MROWS + row]     = E + (size_t)tokens[b * NTOK + 2 * node + 1] * D;
            rowptr[2 * MROWS + row] = E + (size_t)tokens[b * NTOK + 2 * node + 2] * D;
        } else {
            rowptr[MROWS + row]     = g_node_val + ((size_t)(2 * node + 1) * BATCH + b) * D;
            rowptr[2 * MROWS + row] = g_node_val + ((size_t)(2 * node + 2) * BATCH + b) * D;
        }
    }

    float acc[4][JN][4];
    #pragma unroll
    for (int i = 0; i < 4; ++i)
        #pragma unroll
        for (int j = 0; j < JN; ++j)
            #pragma unroll
            for (int q = 0; q < 4; ++q) acc[i][j][q] = 0.f;

    // ---- prologue: W(0) async copy + A(0) gather ----
    {
        const char* src = (const char*)g_W;
        #pragma unroll
        for (int r = 0; r < 8; ++r)
            cp_async16(sbW + tid * 16 + r * 4096, src + tid * 16 + r * 4096);
        cp_commit();
    }
    __syncthreads();   // rowptr visible
    {
        float4 pf[4];
        if (MROWS == 128) {
            int row = tid >> 1, half = tid & 1;
            const float* src = rowptr[row] + half * 16;
            pf[0] = ((const float4*)src)[0]; pf[1] = ((const float4*)src)[1];
            pf[2] = ((const float4*)src)[2]; pf[3] = ((const float4*)src)[3];
            int g_ = row & 7, rhi = (row >> 3) & 1, tmg = row >> 4;
            char* base = As + (tmg * 2 + half) * 512;
            #pragma unroll
            for (int jj = 0; jj < 8; ++jj) {
                uint32_t h, l;
                split2(((const float*)pf)[2 * jj], ((const float*)pf)[2 * jj + 1], h, l);
                int off = (g_ * 4 + (jj & 3)) * 16 + (rhi + 2 * (jj >> 2)) * 4;
                *(uint32_t*)(base + off) = h;
                *(uint32_t*)(base + NT * 1024 + off) = l;
            }
        } else {
            int row = tid >> 2, qt = tid & 3;
            const float* src = rowptr[row] + qt * 8;
            pf[0] = ((const float4*)src)[0]; pf[1] = ((const float4*)src)[1];
            int g_ = row & 7, rhi = (row >> 3) & 1, tmg = row >> 4;
            char* base = As + (tmg * 2 + (qt >> 1)) * 512;
            int kh = qt & 1;
            #pragma unroll
            for (int jj = 0; jj < 4; ++jj) {
                uint32_t h, l;
                split2(((const float*)pf)[2 * jj], ((const float*)pf)[2 * jj + 1], h, l);
                int off = (g_ * 4 + jj) * 16 + (rhi + 2 * kh) * 4;
                *(uint32_t*)(base + off) = h;
                *(uint32_t*)(base + NT * 1024 + off) = l;
            }
        }
    }
    cp_wait<0>();
    __syncthreads();

    // ---- main chunk loop ----
    for (int gc = 0; gc < NCH; ++gc) {
        const int slot = gc & 1;
        const bool doGather = (gc + 1 < 24);

        // prefetch next A rows into registers (global latency hidden by MMAs)
        float4 pf[4];
        if (doGather) {
            int gn = gc + 1;
            if (MROWS == 128) {
                int row = tid >> 1, half = tid & 1;
                const float* src = rowptr[(gn >> 3) * 128 + row] + (gn & 7) * 32 + half * 16;
                pf[0] = ((const float4*)src)[0]; pf[1] = ((const float4*)src)[1];
                pf[2] = ((const float4*)src)[2]; pf[3] = ((const float4*)src)[3];
            } else {
                int row = tid >> 2, qt = tid & 3;
                const float* src = rowptr[(gn >> 3) * 64 + row] + (gn & 7) * 32 + qt * 8;
                pf[0] = ((const float4*)src)[0]; pf[1] = ((const float4*)src)[1];
            }
        }
        // prefetch next W chunk
        if (gc + 1 < NCH) {
            const char* src = (const char*)g_W + (size_t)(gc + 1) * WCHUNK;
            uint32_t dst = sbW + ((gc + 1) & 1) * WCHUNK;
            #pragma unroll
            for (int r = 0; r < 8; ++r)
                cp_async16(dst + tid * 16 + r * 4096, src + tid * 16 + r * 4096);
            cp_commit();
        }

        // ---- compute chunk ----
        const char* Wslot = smem + slot * WCHUNK;
        const int layer = (gc < 24) ? 0 : (gc < 32) ? 1 : 2;
        const int c = (layer == 0) ? 0 : (layer == 1) ? (gc - 24) : (gc - 32);
        #pragma unroll
        for (int ks = 0; ks < 2; ++ks) {
            uint4 Ahi[4], Alo[4];
            if (layer == 0) {
                const char* ab = As + slot * ASLOT;
                #pragma unroll
                for (int i = 0; i < 4; ++i) {
                    const char* p = ab + (((wm * 4 + i) * 2 + ks) * 32 + lane) * 16;
                    Ahi[i] = *(const uint4*)p;
                    Alo[i] = *(const uint4*)(p + NT * 1024);
                }
            } else {
                int sg = c * 2 + ks;
                #pragma unroll
                for (int i = 0; i < 4; ++i) {
                    const char* p = Af + (((wm * 4 + i) * 16 + sg) * 32 + lane) * 16;
                    Ahi[i] = *(const uint4*)p;
                    Alo[i] = *(const uint4*)(p + NT * 8192);
                }
            }
            #pragma unroll
            for (int j = 0; j < JN; ++j) {
                uint4 B = *(const uint4*)(Wslot + ((ks * 32 + wn * JN + j) * 32 + lane) * 16);
                #pragma unroll
                for (int i = 0; i < 4; ++i) {
                    mma16816(acc[i][j], Ahi[i].x, Ahi[i].y, Ahi[i].z, Ahi[i].w, B.x, B.y);
                    mma16816(acc[i][j], Ahi[i].x, Ahi[i].y, Ahi[i].z, Ahi[i].w, B.z, B.w);
                    mma16816(acc[i][j], Alo[i].x, Alo[i].y, Alo[i].z, Alo[i].w, B.x, B.y);
                }
            }
        }

        // store prefetched A rows into the other slot (frag-major, split hi/lo)
        if (doGather) {
            if (MROWS == 128) {
                int row = tid >> 1, half = tid & 1;
                int g_ = row & 7, rhi = (row >> 3) & 1, tmg = row >> 4;
                char* base = As + (slot ^ 1) * ASLOT + (tmg * 2 + half) * 512;
                #pragma unroll
                for (int jj = 0; jj < 8; ++jj) {
                    uint32_t h, l;
                    split2(((const float*)pf)[2 * jj], ((const float*)pf)[2 * jj + 1], h, l);
                    int off = (g_ * 4 + (jj & 3)) * 16 + (rhi + 2 * (jj >> 2)) * 4;
                    *(uint32_t*)(base + off) = h;
                    *(uint32_t*)(base + NT * 1024 + off) = l;
                }
            } else {
                int row = tid >> 2, qt = tid & 3;
                int g_ = row & 7, rhi = (row >> 3) & 1, tmg = row >> 4;
                char* base = As + (slot ^ 1) * ASLOT + (tmg * 2 + (qt >> 1)) * 512;
                int kh = qt & 1;
                #pragma unroll
                for (int jj = 0; jj < 4; ++jj) {
                    uint32_t h, l;
                    split2(((const float*)pf)[2 * jj], ((const float*)pf)[2 * jj + 1], h, l);
                    int off = (g_ * 4 + jj) * 16 + (rhi + 2 * kh) * 4;
                    *(uint32_t*)(base + off) = h;
                    *(uint32_t*)(base + NT * 1024 + off) = l;
                }
            }
        }
        cp_wait<0>();
        __syncthreads();

        // ---- mid epilogue after layers 1 and 2: bias+ELU+split -> Af (frag-major) ----
        if (gc == 23 || gc == 31) {
            const float* bp = bias + ((gc == 23) ? 0 : 256);
            #pragma unroll
            for (int i = 0; i < 4; ++i) {
                int t_m = wm * 4 + i;
                #pragma unroll
                for (int jp = 0; jp < JN / 2; ++jp) {
                    uint4 hv, lv;
                    {
                        int j = 2 * jp;
                        int cb = wn * JN * 8 + j * 8 + tig * 2;
                        float b0v = bp[cb], b1v = bp[cb + 1];
                        float v0 = acc[i][j][0] + b0v, v1 = acc[i][j][1] + b1v;
                        float v2 = acc[i][j][2] + b0v, v3 = acc[i][j][3] + b1v;
                        v0 = v0 > 0.f ? v0 : (__expf(v0) - 1.f);
                        v1 = v1 > 0.f ? v1 : (__expf(v1) - 1.f);
                        v2 = v2 > 0.f ? v2 : (__expf(v2) - 1.f);
                        v3 = v3 > 0.f ? v3 : (__expf(v3) - 1.f);
                        split2(v0, v1, hv.x, lv.x);
                        split2(v2, v3, hv.y, lv.y);
                        acc[i][j][0] = acc[i][j][1] = acc[i][j][2] = acc[i][j][3] = 0.f;
                    }
                    {
                        int j = 2 * jp + 1;
                        int cb = wn * JN * 8 + j * 8 + tig * 2;
                        float b0v = bp[cb], b1v = bp[cb + 1];
                        float v0 = acc[i][j][0] + b0v, v1 = acc[i][j][1] + b1v;
                        float v2 = acc[i][j][2] + b0v, v3 = acc[i][j][3] + b1v;
                        v0 = v0 > 0.f ? v0 : (__expf(v0) - 1.f);
                        v1 = v1 > 0.f ? v1 : (__expf(v1) - 1.f);
                        v2 = v2 > 0.f ? v2 : (__expf(v2) - 1.f);
                        v3 = v3 > 0.f ? v3 : (__expf(v3) - 1.f);
                        split2(v0, v1, hv.z, lv.z);
                        split2(v2, v3, hv.w, lv.w);
                        acc[i][j][0] = acc[i][j][1] = acc[i][j][2] = acc[i][j][3] = 0.f;
                    }
                    int sdst = wn * (JN / 2) + jp;
                    char* p = Af + ((t_m * 16 + sdst) * 32 + lane) * 16;
                    *(uint4*)p = hv;
                    *(uint4*)(p + NT * 8192) = lv;
                }
            }
            __syncthreads();
        }
    }

    // ---- final epilogue: D + b2 -> stage, then residual + coalesced store ----
    #pragma unroll
    for (int i = 0; i < 4; ++i) {
        int r0 = wm * 64 + i * 16 + g;
        #pragma unroll
        for (int j = 0; j < JN; ++j) {
            int cb = wn * JN * 8 + j * 8 + tig * 2;
            float b0v = bias[512 + cb], b1v = bias[512 + cb + 1];
            stage[r0 * 265 + cb]           = acc[i][j][0] + b0v;
            stage[r0 * 265 + cb + 1]       = acc[i][j][1] + b1v;
            stage[(r0 + 8) * 265 + cb]     = acc[i][j][2] + b0v;
            stage[(r0 + 8) * 265 + cb + 1] = acc[i][j][3] + b1v;
        }
    }
    __syncthreads();
    #pragma unroll 1
    for (int it = 0; it < MROWS / 4; ++it) {
        int lin = it * 256 + tid;
        int row = lin >> 6, c4 = lin & 63;
        float4 e = ((const float4*)rowptr[row])[c4];
        const float* sp = stage + row * 265 + c4 * 4;
        float4 ov = make_float4(sp[0] + e.x, sp[1] + e.y, sp[2] + e.z, sp[3] + e.w);
        if (level == 1) {
            ((float4*)(d_out + (size_t)row * D))[c4] = ov;
        } else {
            int node = nA + (row >> 6);
            ((float4*)(g_node_val + ((size_t)node * BATCH + (row & 63)) * D))[c4] = ov;
        }
    }
}

extern "C" void kernel_launch(void* const* d_in, const int* in_sizes, int n_in,
                              void* d_out, int out_size) {
    const int*   tokens = (const int*)d_in[0];
    const float* E      = (const float*)d_in[1];
    const float* W_in   = (const float*)d_in[2];
    const float* b_in   = (const float*)d_in[3];
    const float* W1     = (const float*)d_in[4];
    const float* b1     = (const float*)d_in[5];
    const float* W2     = (const float*)d_in[6];
    const float* b2     = (const float*)d_in[7];
    float* out = (float*)d_out;

    const int SM128 = 65536 + 128 * 265 * 4 + 3072 + 3 * 128 * 8;  // 207360
    const int SM64  = 65536 + 64 * 265 * 4 + 3072 + 3 * 64 * 8;    // 137984
    cudaFuncSetAttribute(level_kernel<128>, cudaFuncAttributeMaxDynamicSharedMemorySize, SM128);
    cudaFuncSetAttribute(level_kernel<64>,  cudaFuncAttributeMaxDynamicSharedMemorySize, SM64);

    prep_weights<<<(NCH * 2048 + 255) / 256, 256>>>(W_in, W1, W2);

    for (int level = 1024; level >= 1; level >>= 1) {
        if (level >= 256) {
            level_kernel<128><<<level / 2, 256, SM128>>>(tokens, E, b_in, b1, b2, out, level);
        } else {
            level_kernel<64><<<level, 256, SM64>>>(tokens, E, b_in, b1, b2, out, level);
        }
    }
}